// round 8
// baseline (speedup 1.0000x reference)
#include <cuda_runtime.h>
#include <cuda_bf16.h>
#include <cuda_fp16.h>
#include <cstdint>

#define NN 50000
#define FE 128
#define NE 640000
#define GT 128            // GEMM tile rows per CTA
#define ST 68             // padded SMEM row stride (u32 units) — conflict-free

#define CSRB 49           // CSR blocks (all co-resident: soft barriers safe)
#define CSRT 1024
#define GSTRIDE (CSRB * CSRT)   // 50176
#define EPT 13            // ceil(NE / GSTRIDE)
#define PFLAG (1 << 25)
#define VMASK 0x00FFFFFF

// ---------------------------------------------------------------------------
// Scratch (__device__ globals: allocation-free rule; zero-init on load)
// ---------------------------------------------------------------------------
__device__ __half   d_Yh[(size_t)NN * FE];  // X @ W (fp16, gather operand)
__device__ int      d_cnt[NN];              // in-degree
__device__ int      d_off[NN];              // CSR offsets
__device__ int      d_srcl[NE];             // bucketed src ids
__device__ int      d_stat[64];             // lookback scan status
__device__ int      d_ctr[4];               // grid-barrier arrival counters

// ---------------------------------------------------------------------------
__device__ __forceinline__ void split_pair(float f0, float f1,
                                           uint32_t& hi, uint32_t& lo) {
    __nv_bfloat162 h2 = __floats2bfloat162_rn(f0, f1);
    float h0 = __bfloat162float(h2.x), h1 = __bfloat162float(h2.y);
    __nv_bfloat162 l2 = __floats2bfloat162_rn(f0 - h0, f1 - h1);
    hi = *(uint32_t*)&h2;
    lo = *(uint32_t*)&l2;
}

__device__ __forceinline__ void mma16816(float* c,
                                         uint32_t a0, uint32_t a1, uint32_t a2, uint32_t a3,
                                         uint32_t b0, uint32_t b1) {
    asm volatile(
        "mma.sync.aligned.m16n8k16.row.col.f32.bf16.bf16.f32 "
        "{%0,%1,%2,%3}, {%4,%5,%6,%7}, {%8,%9}, {%0,%1,%2,%3};"
        : "+f"(c[0]), "+f"(c[1]), "+f"(c[2]), "+f"(c[3])
        : "r"(a0), "r"(a1), "r"(a2), "r"(a3), "r"(b0), "r"(b1));
}

// Software grid barrier (valid: all CSRB blocks co-resident)
__device__ __forceinline__ void gbar(int k) {
    __threadfence();
    __syncthreads();
    if (threadIdx.x == 0) {
        atomicAdd(&d_ctr[k], 1);
        while (atomicOr(&d_ctr[k], 0) < CSRB) __nanosleep(64);
    }
    __syncthreads();
    __threadfence();
}

// ---------------------------------------------------------------------------
// Fused CSR build: zero -> hist (rank in regs) -> lookback scan -> fill.
// One kernel, 49 blocks x 1024 threads, soft grid barriers.
// Pack = (rank << 16) | dst  — both fields < 2^16, stays positive (r7 bugfix).
// ---------------------------------------------------------------------------
__global__ __launch_bounds__(CSRT)
void csr_kernel(const int* __restrict__ edst, const int* __restrict__ esrc) {
    const int tid = threadIdx.x, lane = tid & 31, wid = tid >> 5;
    const int b   = blockIdx.x;
    const int g   = b * CSRT + tid;

    // ---- phase 0: zero counters / scan state ----
    if (g < NN) d_cnt[g] = 0;
    if (g < 64) d_stat[g] = 0;
    gbar(0);

    // ---- phase 1: histogram; keep (rank, dst) packed in registers ----
    uint32_t pk[EPT];
    #pragma unroll
    for (int k = 0; k < EPT; ++k) {
        int e = g + k * GSTRIDE;
        pk[k] = 0;
        if (e < NE) {
            uint32_t d = (uint32_t)edst[e];
            uint32_t r = (uint32_t)atomicAdd(&d_cnt[d], 1);
            pk[k] = (r << 16) | d;       // r << 2^15, d < 2^16
        }
    }
    gbar(1);

    // ---- phase 2: decoupled-lookback exclusive scan of d_cnt -> d_off ----
    {
        __shared__ int wsum[32];
        __shared__ int s_total;
        __shared__ int s_prefix;
        const int i = b * CSRT + tid;
        int x = (i < NN) ? d_cnt[i] : 0;
        int v = x;
        #pragma unroll
        for (int o = 1; o < 32; o <<= 1) {
            int t = __shfl_up_sync(0xffffffffu, v, o);
            if (lane >= o) v += t;
        }
        if (lane == 31) wsum[wid] = v;
        __syncthreads();
        if (tid < 32) {
            int s = wsum[tid];
            int sv = s;
            #pragma unroll
            for (int o = 1; o < 32; o <<= 1) {
                int t = __shfl_up_sync(0xffffffffu, sv, o);
                if (tid >= o) sv += t;
            }
            wsum[tid] = sv - s;
            if (tid == 31) s_total = sv;
        }
        __syncthreads();

        if (wid == 0) {
            int total = s_total;
            if (b == 0) {
                if (lane == 0) {
                    atomicExch(&d_stat[0], PFLAG | total);
                    s_prefix = 0;
                }
            } else {
                if (lane == 0) atomicExch(&d_stat[b], (1 << 24) | total);
                int run = 0, base = b - 1;
                for (;;) {
                    int idx = base - lane;
                    int s = 0;
                    if (idx >= 0) {
                        do { s = atomicOr(&d_stat[idx], 0); } while (s == 0);
                    }
                    unsigned pm = __ballot_sync(0xffffffffu, idx >= 0 && (s & PFLAG));
                    int lim = pm ? (__ffs(pm) - 1) : 31;
                    int contrib = (idx >= 0 && lane <= lim) ? (s & VMASK) : 0;
                    #pragma unroll
                    for (int o = 16; o > 0; o >>= 1)
                        contrib += __shfl_down_sync(0xffffffffu, contrib, o);
                    run += __shfl_sync(0xffffffffu, contrib, 0);
                    if (pm) break;
                    base -= 32;
                }
                if (lane == 0) {
                    atomicExch(&d_stat[b], PFLAG | (run + total));
                    s_prefix = run;
                }
            }
        }
        __syncthreads();
        if (i < NN) d_off[i] = s_prefix + wsum[wid] + (v - x);
    }
    gbar(2);

    // ---- phase 3: atomic-free fill from register-held (rank, dst) ----
    #pragma unroll
    for (int k = 0; k < EPT; ++k) {
        int e = g + k * GSTRIDE;
        if (e < NE) {
            uint32_t p = pk[k];
            d_srcl[d_off[p & 0xffffu] + (p >> 16)] = esrc[e];
        }
    }

    // ---- cleanup: last block to arrive resets barrier counters ----
    __threadfence();
    __syncthreads();
    if (tid == 0) {
        if (atomicAdd(&d_ctr[3], 1) == CSRB - 1) {
            d_ctr[0] = 0; d_ctr[1] = 0; d_ctr[2] = 0; d_ctr[3] = 0;
            __threadfence();
        }
    }
}

// ---------------------------------------------------------------------------
// GEMM via mma.sync bf16 3-term split; W converted inline (bf16 hi/lo).
// 256 thr (8 warps), 128-row tile, 4x2 warp tiling.
// Epilogue: Y -> fp16 scratch, relu(Y) -> out[:, 0:128].
// ---------------------------------------------------------------------------
#define XH_OFF 0
#define XL_OFF 8704
#define WH_OFF 17408
#define WL_OFF 26112
#define SM_U32 34816
#define SM_BYTES (SM_U32 * 4)

__global__ __launch_bounds__(256, 1)
void gemm_tc_kernel(const float* __restrict__ X, const float* __restrict__ W,
                    float* __restrict__ out) {
    extern __shared__ uint32_t smu[];
    const int tid  = threadIdx.x;
    const int wid  = tid >> 5, lane = tid & 31;
    const int g    = lane >> 2, tig = lane & 3;
    const int row0 = blockIdx.x * GT;

    // Stage W: load fp32 (coalesced over n), split, store pair (2k,2k+1) at kp
    #pragma unroll
    for (int i = 0; i < 32; ++i) {
        int q  = i * 256 + tid;         // 8192 items
        int kp = q >> 7, n = q & 127;
        float w0 = W[(2 * kp)     * FE + n];
        float w1 = W[(2 * kp + 1) * FE + n];
        uint32_t hi, lo;
        split_pair(w0, w1, hi, lo);
        smu[WH_OFF + n * ST + kp] = hi;
        smu[WL_OFF + n * ST + kp] = lo;
    }
    // Stage X tile: load fp32, split to bf16 hi/lo pairs
    #pragma unroll
    for (int i = 0; i < 16; ++i) {
        int q  = i * 256 + tid;
        int r  = q >> 5, c4 = q & 31;
        float4 v = make_float4(0.f, 0.f, 0.f, 0.f);
        if (row0 + r < NN) v = ((const float4*)X)[(size_t)(row0 + r) * 32 + c4];
        uint32_t h01, l01, h23, l23;
        split_pair(v.x, v.y, h01, l01);
        split_pair(v.z, v.w, h23, l23);
        uint32_t o = r * ST + c4 * 2;
        smu[XH_OFF + o]     = h01;
        smu[XH_OFF + o + 1] = h23;
        smu[XL_OFF + o]     = l01;
        smu[XL_OFF + o + 1] = l23;
    }
    __syncthreads();

    const int rw = (wid & 3) * 32;
    const int cw = (wid >> 2) * 64;

    float acc[2][8][4];
    #pragma unroll
    for (int t = 0; t < 2; ++t)
        #pragma unroll
        for (int j = 0; j < 8; ++j)
            #pragma unroll
            for (int q = 0; q < 4; ++q) acc[t][j][q] = 0.f;

    #pragma unroll
    for (int ks = 0; ks < 8; ++ks) {
        const int kb = ks * 8;
        uint32_t ah[2][4], al[2][4];
        #pragma unroll
        for (int t = 0; t < 2; ++t) {
            uint32_t r0 = (rw + t * 16 + g) * ST + kb + tig;
            uint32_t r8 = r0 + 8 * ST;
            ah[t][0] = smu[XH_OFF + r0];
            ah[t][1] = smu[XH_OFF + r8];
            ah[t][2] = smu[XH_OFF + r0 + 4];
            ah[t][3] = smu[XH_OFF + r8 + 4];
            al[t][0] = smu[XL_OFF + r0];
            al[t][1] = smu[XL_OFF + r8];
            al[t][2] = smu[XL_OFF + r0 + 4];
            al[t][3] = smu[XL_OFF + r8 + 4];
        }
        #pragma unroll
        for (int j = 0; j < 8; ++j) {
            uint32_t bo  = (cw + j * 8 + g) * ST + kb + tig;
            uint32_t bh0 = smu[WH_OFF + bo];
            uint32_t bh1 = smu[WH_OFF + bo + 4];
            uint32_t bl0 = smu[WL_OFF + bo];
            uint32_t bl1 = smu[WL_OFF + bo + 4];
            #pragma unroll
            for (int t = 0; t < 2; ++t) {
                mma16816(acc[t][j], ah[t][0], ah[t][1], ah[t][2], ah[t][3], bh0, bh1);
                mma16816(acc[t][j], ah[t][0], ah[t][1], ah[t][2], ah[t][3], bl0, bl1);
                mma16816(acc[t][j], al[t][0], al[t][1], al[t][2], al[t][3], bh0, bh1);
            }
        }
    }

    #pragma unroll
    for (int t = 0; t < 2; ++t) {
        #pragma unroll
        for (int j = 0; j < 8; ++j) {
            int col = cw + j * 8 + tig * 2;
            #pragma unroll
            for (int h = 0; h < 2; ++h) {
                int r = row0 + rw + t * 16 + g + h * 8;
                if (r < NN) {
                    float y0 = acc[t][j][h * 2], y1 = acc[t][j][h * 2 + 1];
                    *(__half2*)&d_Yh[(size_t)r * FE + col] =
                        __float22half2_rn(make_float2(y0, y1));
                    *(float2*)&out[(size_t)r * 256 + col] =
                        make_float2(fmaxf(y0, 0.f), fmaxf(y1, 0.f));
                }
            }
        }
    }
}

// ---------------------------------------------------------------------------
// Atomic-free aggregation: one warp per dst node; fp16 gather, fp32 accum.
// ---------------------------------------------------------------------------
__global__ __launch_bounds__(256)
void agg_kernel(float* __restrict__ out) {
    int g    = blockIdx.x * blockDim.x + threadIdx.x;
    int n    = g >> 5;
    int lane = g & 31;
    if (n >= NN) return;

    int deg  = d_cnt[n];
    int base = d_off[n];
    float4 acc = make_float4(0.f, 0.f, 0.f, 0.f);

    int i = 0;
    for (; i + 4 <= deg; i += 4) {
        int s0 = d_srcl[base + i + 0];
        int s1 = d_srcl[base + i + 1];
        int s2 = d_srcl[base + i + 2];
        int s3 = d_srcl[base + i + 3];
        uint2 u0 = ((const uint2*)(d_Yh + (size_t)s0 * FE))[lane];
        uint2 u1 = ((const uint2*)(d_Yh + (size_t)s1 * FE))[lane];
        uint2 u2 = ((const uint2*)(d_Yh + (size_t)s2 * FE))[lane];
        uint2 u3 = ((const uint2*)(d_Yh + (size_t)s3 * FE))[lane];
        float2 a0 = __half22float2(*(__half2*)&u0.x), b0 = __half22float2(*(__half2*)&u0.y);
        float2 a1 = __half22float2(*(__half2*)&u1.x), b1 = __half22float2(*(__half2*)&u1.y);
        float2 a2 = __half22float2(*(__half2*)&u2.x), b2 = __half22float2(*(__half2*)&u2.y);
        float2 a3 = __half22float2(*(__half2*)&u3.x), b3 = __half22float2(*(__half2*)&u3.y);
        acc.x += (a0.x + a1.x) + (a2.x + a3.x);
        acc.y += (a0.y + a1.y) + (a2.y + a3.y);
        acc.z += (b0.x + b1.x) + (b2.x + b3.x);
        acc.w += (b0.y + b1.y) + (b2.y + b3.y);
    }
    for (; i < deg; ++i) {
        int s = d_srcl[base + i];
        uint2 u = ((const uint2*)(d_Yh + (size_t)s * FE))[lane];
        float2 a = __half22float2(*(__half2*)&u.x), b = __half22float2(*(__half2*)&u.y);
        acc.x += a.x; acc.y += a.y; acc.z += b.x; acc.w += b.y;
    }

    float inv = (deg > 0) ? (1.0f / (float)deg) : 0.0f;
    float4 r = make_float4(fmaxf(acc.x * inv, 0.f), fmaxf(acc.y * inv, 0.f),
                           fmaxf(acc.z * inv, 0.f), fmaxf(acc.w * inv, 0.f));
    ((float4*)(out + (size_t)n * 256 + 128))[lane] = r;
}

// ---------------------------------------------------------------------------
extern "C" void kernel_launch(void* const* d_in, const int* in_sizes, int n_in,
                              void* d_out, int out_size) {
    const float* X    = (const float*)d_in[0];
    const float* W    = (const float*)d_in[1];
    const int*   edst = (const int*)d_in[2];
    const int*   esrc = (const int*)d_in[3];
    float*       out  = (float*)d_out;

    cudaFuncSetAttribute(gemm_tc_kernel,
                         cudaFuncAttributeMaxDynamicSharedMemorySize, SM_BYTES);

    csr_kernel<<<CSRB, CSRT>>>(edst, esrc);
    gemm_tc_kernel<<<(NN + GT - 1) / GT, 256, SM_BYTES>>>(X, W, out);
    agg_kernel<<<(NN * 32 + 255) / 256, 256>>>(out);
}

// round 9
// speedup vs baseline: 1.1533x; 1.1533x over previous
#include <cuda_runtime.h>
#include <cuda_bf16.h>
#include <cuda_fp16.h>
#include <cstdint>

#define NN 50000
#define FE 128
#define NE 640000
#define GT 128            // GEMM tile rows per CTA
#define ST 68             // padded SMEM row stride (u32 units) — conflict-free

#define CSRB 148          // one CTA per SM — co-resident, full chip
#define CSRT 1024
#define GSTRIDE (CSRB * CSRT)   // 151552
#define EPT 5             // ceil(NE / GSTRIDE)
#define PFLAG (1 << 25)
#define VMASK 0x00FFFFFF

// ---------------------------------------------------------------------------
// Scratch (__device__ globals: allocation-free rule; zero-init on load)
// ---------------------------------------------------------------------------
__device__ __half   d_Yh[(size_t)NN * FE];  // X @ W (fp16, gather operand)
__device__ int      d_cnt[NN];              // in-degree
__device__ int      d_off[NN];              // CSR offsets
__device__ int      d_srcl[NE];             // bucketed src ids
__device__ int      d_stat[160];            // lookback scan status
__device__ int      d_ctr[4];               // grid-barrier arrival counters

// ---------------------------------------------------------------------------
__device__ __forceinline__ void split_pair(float f0, float f1,
                                           uint32_t& hi, uint32_t& lo) {
    __nv_bfloat162 h2 = __floats2bfloat162_rn(f0, f1);
    float h0 = __bfloat162float(h2.x), h1 = __bfloat162float(h2.y);
    __nv_bfloat162 l2 = __floats2bfloat162_rn(f0 - h0, f1 - h1);
    hi = *(uint32_t*)&h2;
    lo = *(uint32_t*)&l2;
}

__device__ __forceinline__ void mma16816(float* c,
                                         uint32_t a0, uint32_t a1, uint32_t a2, uint32_t a3,
                                         uint32_t b0, uint32_t b1) {
    asm volatile(
        "mma.sync.aligned.m16n8k16.row.col.f32.bf16.bf16.f32 "
        "{%0,%1,%2,%3}, {%4,%5,%6,%7}, {%8,%9}, {%0,%1,%2,%3};"
        : "+f"(c[0]), "+f"(c[1]), "+f"(c[2]), "+f"(c[3])
        : "r"(a0), "r"(a1), "r"(a2), "r"(a3), "r"(b0), "r"(b1));
}

// Software grid barrier (valid: all CSRB blocks co-resident at 1 CTA/SM)
__device__ __forceinline__ void gbar(int k) {
    __threadfence();
    __syncthreads();
    if (threadIdx.x == 0) {
        atomicAdd(&d_ctr[k], 1);
        while (atomicOr(&d_ctr[k], 0) < CSRB) __nanosleep(64);
    }
    __syncthreads();
    __threadfence();
}

// ---------------------------------------------------------------------------
// Fused CSR build: zero -> hist (rank in regs) -> lookback scan -> fill.
// One kernel, 148 blocks x 1024 threads (full chip), soft grid barriers.
// Pack = (rank << 16) | dst, unsigned — both fields < 2^16.
// ---------------------------------------------------------------------------
__global__ __launch_bounds__(CSRT)
void csr_kernel(const int* __restrict__ edst, const int* __restrict__ esrc) {
    const int tid = threadIdx.x, lane = tid & 31, wid = tid >> 5;
    const int b   = blockIdx.x;
    const int g   = b * CSRT + tid;

    // ---- phase 0: zero counters / scan state ----
    if (g < NN) d_cnt[g] = 0;
    if (g >= NN && g < NN + 160) d_stat[g - NN] = 0;
    gbar(0);

    // ---- phase 1: histogram; keep (rank, dst) packed in registers ----
    uint32_t pk[EPT];
    #pragma unroll
    for (int k = 0; k < EPT; ++k) {
        int e = g + k * GSTRIDE;
        pk[k] = 0;
        if (e < NE) {
            uint32_t d = (uint32_t)edst[e];
            uint32_t r = (uint32_t)atomicAdd(&d_cnt[d], 1);
            pk[k] = (r << 16) | d;
        }
    }
    gbar(1);

    // ---- phase 2: decoupled-lookback exclusive scan of d_cnt -> d_off ----
    {
        __shared__ int wsum[32];
        __shared__ int s_total;
        __shared__ int s_prefix;
        const int i = b * CSRT + tid;
        int x = (i < NN) ? d_cnt[i] : 0;
        int v = x;
        #pragma unroll
        for (int o = 1; o < 32; o <<= 1) {
            int t = __shfl_up_sync(0xffffffffu, v, o);
            if (lane >= o) v += t;
        }
        if (lane == 31) wsum[wid] = v;
        __syncthreads();
        if (tid < 32) {
            int s = wsum[tid];
            int sv = s;
            #pragma unroll
            for (int o = 1; o < 32; o <<= 1) {
                int t = __shfl_up_sync(0xffffffffu, sv, o);
                if (tid >= o) sv += t;
            }
            wsum[tid] = sv - s;
            if (tid == 31) s_total = sv;
        }
        __syncthreads();

        if (wid == 0) {
            int total = s_total;
            if (b == 0) {
                if (lane == 0) {
                    atomicExch(&d_stat[0], PFLAG | total);
                    s_prefix = 0;
                }
            } else {
                if (lane == 0) atomicExch(&d_stat[b], (1 << 24) | total);
                int run = 0, base = b - 1;
                for (;;) {
                    int idx = base - lane;
                    int s = 0;
                    if (idx >= 0) {
                        do { s = atomicOr(&d_stat[idx], 0); } while (s == 0);
                    }
                    unsigned pm = __ballot_sync(0xffffffffu, idx >= 0 && (s & PFLAG));
                    int lim = pm ? (__ffs(pm) - 1) : 31;
                    int contrib = (idx >= 0 && lane <= lim) ? (s & VMASK) : 0;
                    #pragma unroll
                    for (int o = 16; o > 0; o >>= 1)
                        contrib += __shfl_down_sync(0xffffffffu, contrib, o);
                    run += __shfl_sync(0xffffffffu, contrib, 0);
                    if (pm) break;
                    base -= 32;
                }
                if (lane == 0) {
                    atomicExch(&d_stat[b], PFLAG | (run + total));
                    s_prefix = run;
                }
            }
        }
        __syncthreads();
        if (i < NN) d_off[i] = s_prefix + wsum[wid] + (v - x);
    }
    gbar(2);

    // ---- phase 3: atomic-free fill from register-held (rank, dst) ----
    #pragma unroll
    for (int k = 0; k < EPT; ++k) {
        int e = g + k * GSTRIDE;
        if (e < NE) {
            uint32_t p = pk[k];
            d_srcl[d_off[p & 0xffffu] + (p >> 16)] = esrc[e];
        }
    }

    // ---- cleanup: last block to arrive resets barrier counters ----
    __threadfence();
    __syncthreads();
    if (tid == 0) {
        if (atomicAdd(&d_ctr[3], 1) == CSRB - 1) {
            d_ctr[0] = 0; d_ctr[1] = 0; d_ctr[2] = 0; d_ctr[3] = 0;
            __threadfence();
        }
    }
}

// ---------------------------------------------------------------------------
// GEMM via mma.sync bf16 3-term split; W converted inline (bf16 hi/lo).
// 256 thr (8 warps), 128-row tile, 4x2 warp tiling.
// Epilogue: Y -> fp16 scratch, relu(Y) -> out[:, 0:128].
// ---------------------------------------------------------------------------
#define XH_OFF 0
#define XL_OFF 8704
#define WH_OFF 17408
#define WL_OFF 26112
#define SM_U32 34816
#define SM_BYTES (SM_U32 * 4)

__global__ __launch_bounds__(256, 1)
void gemm_tc_kernel(const float* __restrict__ X, const float* __restrict__ W,
                    float* __restrict__ out) {
    extern __shared__ uint32_t smu[];
    const int tid  = threadIdx.x;
    const int wid  = tid >> 5, lane = tid & 31;
    const int g    = lane >> 2, tig = lane & 3;
    const int row0 = blockIdx.x * GT;

    // Stage W: load fp32 (coalesced over n), split, store pair (2k,2k+1) at kp
    #pragma unroll
    for (int i = 0; i < 32; ++i) {
        int q  = i * 256 + tid;         // 8192 items
        int kp = q >> 7, n = q & 127;
        float w0 = W[(2 * kp)     * FE + n];
        float w1 = W[(2 * kp + 1) * FE + n];
        uint32_t hi, lo;
        split_pair(w0, w1, hi, lo);
        smu[WH_OFF + n * ST + kp] = hi;
        smu[WL_OFF + n * ST + kp] = lo;
    }
    // Stage X tile: load fp32, split to bf16 hi/lo pairs
    #pragma unroll
    for (int i = 0; i < 16; ++i) {
        int q  = i * 256 + tid;
        int r  = q >> 5, c4 = q & 31;
        float4 v = make_float4(0.f, 0.f, 0.f, 0.f);
        if (row0 + r < NN) v = ((const float4*)X)[(size_t)(row0 + r) * 32 + c4];
        uint32_t h01, l01, h23, l23;
        split_pair(v.x, v.y, h01, l01);
        split_pair(v.z, v.w, h23, l23);
        uint32_t o = r * ST + c4 * 2;
        smu[XH_OFF + o]     = h01;
        smu[XH_OFF + o + 1] = h23;
        smu[XL_OFF + o]     = l01;
        smu[XL_OFF + o + 1] = l23;
    }
    __syncthreads();

    const int rw = (wid & 3) * 32;
    const int cw = (wid >> 2) * 64;

    float acc[2][8][4];
    #pragma unroll
    for (int t = 0; t < 2; ++t)
        #pragma unroll
        for (int j = 0; j < 8; ++j)
            #pragma unroll
            for (int q = 0; q < 4; ++q) acc[t][j][q] = 0.f;

    #pragma unroll
    for (int ks = 0; ks < 8; ++ks) {
        const int kb = ks * 8;
        uint32_t ah[2][4], al[2][4];
        #pragma unroll
        for (int t = 0; t < 2; ++t) {
            uint32_t r0 = (rw + t * 16 + g) * ST + kb + tig;
            uint32_t r8 = r0 + 8 * ST;
            ah[t][0] = smu[XH_OFF + r0];
            ah[t][1] = smu[XH_OFF + r8];
            ah[t][2] = smu[XH_OFF + r0 + 4];
            ah[t][3] = smu[XH_OFF + r8 + 4];
            al[t][0] = smu[XL_OFF + r0];
            al[t][1] = smu[XL_OFF + r8];
            al[t][2] = smu[XL_OFF + r0 + 4];
            al[t][3] = smu[XL_OFF + r8 + 4];
        }
        #pragma unroll
        for (int j = 0; j < 8; ++j) {
            uint32_t bo  = (cw + j * 8 + g) * ST + kb + tig;
            uint32_t bh0 = smu[WH_OFF + bo];
            uint32_t bh1 = smu[WH_OFF + bo + 4];
            uint32_t bl0 = smu[WL_OFF + bo];
            uint32_t bl1 = smu[WL_OFF + bo + 4];
            #pragma unroll
            for (int t = 0; t < 2; ++t) {
                mma16816(acc[t][j], ah[t][0], ah[t][1], ah[t][2], ah[t][3], bh0, bh1);
                mma16816(acc[t][j], ah[t][0], ah[t][1], ah[t][2], ah[t][3], bl0, bl1);
                mma16816(acc[t][j], al[t][0], al[t][1], al[t][2], al[t][3], bh0, bh1);
            }
        }
    }

    #pragma unroll
    for (int t = 0; t < 2; ++t) {
        #pragma unroll
        for (int j = 0; j < 8; ++j) {
            int col = cw + j * 8 + tig * 2;
            #pragma unroll
            for (int h = 0; h < 2; ++h) {
                int r = row0 + rw + t * 16 + g + h * 8;
                if (r < NN) {
                    float y0 = acc[t][j][h * 2], y1 = acc[t][j][h * 2 + 1];
                    *(__half2*)&d_Yh[(size_t)r * FE + col] =
                        __float22half2_rn(make_float2(y0, y1));
                    *(float2*)&out[(size_t)r * 256 + col] =
                        make_float2(fmaxf(y0, 0.f), fmaxf(y1, 0.f));
                }
            }
        }
    }
}

// ---------------------------------------------------------------------------
// Atomic-free aggregation: one warp per dst node; fp16 gather, fp32 accum.
// ---------------------------------------------------------------------------
__global__ __launch_bounds__(256)
void agg_kernel(float* __restrict__ out) {
    int g    = blockIdx.x * blockDim.x + threadIdx.x;
    int n    = g >> 5;
    int lane = g & 31;
    if (n >= NN) return;

    int deg  = d_cnt[n];
    int base = d_off[n];
    float4 acc = make_float4(0.f, 0.f, 0.f, 0.f);

    int i = 0;
    for (; i + 4 <= deg; i += 4) {
        int s0 = d_srcl[base + i + 0];
        int s1 = d_srcl[base + i + 1];
        int s2 = d_srcl[base + i + 2];
        int s3 = d_srcl[base + i + 3];
        uint2 u0 = ((const uint2*)(d_Yh + (size_t)s0 * FE))[lane];
        uint2 u1 = ((const uint2*)(d_Yh + (size_t)s1 * FE))[lane];
        uint2 u2 = ((const uint2*)(d_Yh + (size_t)s2 * FE))[lane];
        uint2 u3 = ((const uint2*)(d_Yh + (size_t)s3 * FE))[lane];
        float2 a0 = __half22float2(*(__half2*)&u0.x), b0 = __half22float2(*(__half2*)&u0.y);
        float2 a1 = __half22float2(*(__half2*)&u1.x), b1 = __half22float2(*(__half2*)&u1.y);
        float2 a2 = __half22float2(*(__half2*)&u2.x), b2 = __half22float2(*(__half2*)&u2.y);
        float2 a3 = __half22float2(*(__half2*)&u3.x), b3 = __half22float2(*(__half2*)&u3.y);
        acc.x += (a0.x + a1.x) + (a2.x + a3.x);
        acc.y += (a0.y + a1.y) + (a2.y + a3.y);
        acc.z += (b0.x + b1.x) + (b2.x + b3.x);
        acc.w += (b0.y + b1.y) + (b2.y + b3.y);
    }
    for (; i < deg; ++i) {
        int s = d_srcl[base + i];
        uint2 u = ((const uint2*)(d_Yh + (size_t)s * FE))[lane];
        float2 a = __half22float2(*(__half2*)&u.x), b = __half22float2(*(__half2*)&u.y);
        acc.x += a.x; acc.y += a.y; acc.z += b.x; acc.w += b.y;
    }

    float inv = (deg > 0) ? (1.0f / (float)deg) : 0.0f;
    float4 r = make_float4(fmaxf(acc.x * inv, 0.f), fmaxf(acc.y * inv, 0.f),
                           fmaxf(acc.z * inv, 0.f), fmaxf(acc.w * inv, 0.f));
    ((float4*)(out + (size_t)n * 256 + 128))[lane] = r;
}

// ---------------------------------------------------------------------------
extern "C" void kernel_launch(void* const* d_in, const int* in_sizes, int n_in,
                              void* d_out, int out_size) {
    const float* X    = (const float*)d_in[0];
    const float* W    = (const float*)d_in[1];
    const int*   edst = (const int*)d_in[2];
    const int*   esrc = (const int*)d_in[3];
    float*       out  = (float*)d_out;

    cudaFuncSetAttribute(gemm_tc_kernel,
                         cudaFuncAttributeMaxDynamicSharedMemorySize, SM_BYTES);

    csr_kernel<<<CSRB, CSRT>>>(edst, esrc);
    gemm_tc_kernel<<<(NN + GT - 1) / GT, 256, SM_BYTES>>>(X, W, out);
    agg_kernel<<<(NN * 32 + 255) / 256, 256>>>(out);
}